// round 13
// baseline (speedup 1.0000x reference)
#include <cuda_runtime.h>
#include <cuda_fp16.h>
#include <math.h>
#include <stdint.h>

#define BB 16
#define L1 32
#define L2 128
#define DEC 512
#define MEMD 512
#define TOPN 50

// Scratch (allocation-free rule: __device__ globals)
__device__ float    g_f1p[8 * BB * DEC];     // 8-way K-split partials
__device__ float    g_f2p[8 * BB * DEC];
__device__ float    g_doc_score[BB * L1];
__device__ uint32_t g_Wmh[DEC * MEMD / 2];   // Wm as half2 pairs
__device__ float    g_ctxp[BB * L1 * MEMD];  // per-(b,q) partial context

// ============================ helpers =====================================
__device__ __forceinline__ uint32_t smem_u32(const void* p) {
    uint32_t a;
    asm("{ .reg .u64 t; cvta.to.shared.u64 t, %1; cvt.u32.u64 %0, t; }"
        : "=r"(a) : "l"(p));
    return a;
}
#define CP_ASYNC16(dst_u32, src_ptr) \
    asm volatile("cp.async.cg.shared.global [%0], [%1], 16;" \
                 :: "r"(dst_u32), "l"(src_ptr) : "memory")
#define CP_COMMIT() asm volatile("cp.async.commit_group;" ::: "memory")
#define CP_WAIT0()  asm volatile("cp.async.wait_group 0;" ::: "memory")
#define CP_WAIT1()  asm volatile("cp.async.wait_group 1;" ::: "memory")

#define LDSM_X4(R0, R1, R2, R3, addr) \
    asm volatile("ldmatrix.sync.aligned.m8n8.x4.shared.b16 {%0,%1,%2,%3}, [%4];" \
        : "=r"(R0), "=r"(R1), "=r"(R2), "=r"(R3) : "r"(addr))

__device__ __forceinline__ float tanh_hw(float x) {
    float y;
    asm("tanh.approx.f32 %0, %1;" : "=f"(y) : "f"(x));
    return y;
}

__device__ __forceinline__ void mma_f16(float* c, const uint32_t* a, const uint32_t* b) {
    asm volatile(
        "mma.sync.aligned.m16n8k16.row.col.f32.f16.f16.f32 "
        "{%0,%1,%2,%3}, {%4,%5,%6,%7}, {%8,%9}, {%0,%1,%2,%3};"
        : "+f"(c[0]), "+f"(c[1]), "+f"(c[2]), "+f"(c[3])
        : "r"(a[0]), "r"(a[1]), "r"(a[2]), "r"(a[3]), "r"(b[0]), "r"(b[1]));
}

__device__ __forceinline__ uint32_t pack_h2(float x, float y) {
    __half2 h = __floats2half2_rn(x, y);
    return *(uint32_t*)&h;
}

// ---------------------------------------------------------------------------
// Kernel A: grid 288 x 256.
// Blocks 0..31:  f1/f2 — block=(mat, 32-d chunk); thread=(d_local, k-eighth).
//                f[16] accumulators over all b (weight reuse + wide ILP).
// Blocks 32..287: Wm -> fp16 conversion (1 float4 per thread) + zero scores.
// ---------------------------------------------------------------------------
__global__ void prep_kernel(const float* __restrict__ dec,
                            const float* __restrict__ topic,
                            const float* __restrict__ Wd,
                            const float* __restrict__ Wt,
                            const float* __restrict__ Wd2,
                            const float* __restrict__ Wt2,
                            const float* __restrict__ Wm) {
    const int tid = threadIdx.x;
    const int blk = blockIdx.x;

    if (blk >= 32) {
        // ---- Wm conversion blocks ----
        const int idx = (blk - 32) * 256 + tid;   // 0..65535
        float4 v = ((const float4*)Wm)[idx];
        g_Wmh[idx * 2]     = pack_h2(v.x, v.y);
        g_Wmh[idx * 2 + 1] = pack_h2(v.z, v.w);
        if (idx < BB * L1) g_doc_score[idx] = 0.f;
        return;
    }

    // ---- f1/f2 blocks ----
    __shared__ float sdec[BB * DEC];    // 32 KB
    __shared__ float stop[BB * TOPN];   // 3.2 KB
    for (int i = tid; i < BB * DEC; i += 256) sdec[i] = dec[i];
    for (int i = tid; i < BB * TOPN; i += 256) stop[i] = topic[i];
    __syncthreads();

    const int mat = blk & 1;            // 0: f1 (Wd/Wt), 1: f2 (Wd2/Wt2)
    const int dch = blk >> 1;           // 0..15 (32 d-rows each)
    const int dl  = tid >> 3;           // 0..31
    const int kq  = tid & 7;            // k-eighth (64 floats)
    const int d   = dch * 32 + dl;
    const int k0  = kq * 64;

    const float4* W4 = (const float4*)((mat ? Wd2 : Wd) + (size_t)d * DEC + k0);
    const float*  WT = (mat ? Wt2 : Wt) + (size_t)d * TOPN;
    float* out = (mat ? g_f2p : g_f1p) + kq * (BB * DEC) + d;

    float f[BB];
#pragma unroll
    for (int b = 0; b < BB; ++b) f[b] = 0.f;

#pragma unroll 4
    for (int m = 0; m < 16; ++m) {
        float4 w = W4[m];
#pragma unroll
        for (int b = 0; b < BB; ++b) {
            const float4 dv = *(const float4*)(sdec + b * DEC + k0 + m * 4);
            f[b] += w.x * dv.x + w.y * dv.y + w.z * dv.z + w.w * dv.w;
        }
    }
    if (kq == 7) {                      // topic term rides on one part
        for (int t = 0; t < TOPN; ++t) {
            float wt = WT[t];
#pragma unroll
            for (int b = 0; b < BB; ++b)
                f[b] += wt * stop[b * TOPN + t];
        }
    }
#pragma unroll
    for (int b = 0; b < BB; ++b)
        out[b * DEC] = f[b];
}

// ---------------------------------------------------------------------------
// Kernel B (fused, 512 threads = 16 warps, 4m x 4n, warp tile 32x64):
// blocks [0,512): word-level fp16 GEMM (ldmatrix + mma m16n8k16)
//   + tanh + Wv-reduce + softmax + partial context from resident A tile.
// blocks [512,640): doc-level partial scores.
// (Mainloop identical to the best-measured R7 configuration.)
// ---------------------------------------------------------------------------
#define AW 260                      // A row stride in 32-bit words
#define BW 20                       // B row stride in 32-bit words
#define BBUF_BYTES 20480            // 256*BW*4
#define OFF_BBUF 133120             // after A tile (128*260*4)
#define OFF_F    194560             // after 3 B buffers
#define OFF_V    196608
#define OFF_SC   198656
#define OFF_RD   199168
#define SMEM_BYTES 199296

__global__ __launch_bounds__(512, 1)
void word_attn_tc(const float* __restrict__ wmem,   // [B,L1,L2,MEM]
                  const float* __restrict__ Wv,     // [DEC]
                  const int*   __restrict__ wmask,  // [B,L1,L2]
                  float* __restrict__ attn_out,     // [B,L1,L2]
                  const float* __restrict__ dmem,   // [B,L1,MEM]
                  const float* __restrict__ Wm2,    // [DEC,MEM]
                  const float* __restrict__ Wv2) {  // [DEC]
    extern __shared__ char smem[];
    const int tid = threadIdx.x;

    // ======================= doc-score blocks ============================
    if (blockIdx.x >= BB * L1) {
        float* sdoc = (float*)smem;           // 32*512 floats = 64KB
        const int blk = blockIdx.x - BB * L1; // 0..127
        const int b   = blk >> 3;
        const int dc  = blk & 7;

        const float* drow = dmem + (size_t)b * L1 * MEMD;
        for (int i = tid; i < L1 * MEMD; i += 512) sdoc[i] = drow[i];
        __syncthreads();

        const int q    = tid >> 4;          // 0..31
        const int dsub = tid & 15;          // 4 d each
        float acc = 0.f;
        for (int k = 0; k < 4; ++k) {
            const int d = dc * 64 + dsub * 4 + k;
            const float4* w = (const float4*)(Wm2 + (size_t)d * MEMD);
            const float4* x = (const float4*)(sdoc + q * MEMD);
            float s0 = 0.f;
#pragma unroll 8
            for (int mm = 0; mm < 128; ++mm) {
                float4 wv = w[mm], xv = x[mm];
                s0 += wv.x * xv.x + wv.y * xv.y + wv.z * xv.z + wv.w * xv.w;
            }
            const int fi = b * DEC + d;
            float f2v = 0.f;
#pragma unroll
            for (int p = 0; p < 8; ++p) f2v += g_f2p[p * (BB * DEC) + fi];
            acc += tanh_hw(s0 + f2v) * Wv2[d];
        }
        atomicAdd(&g_doc_score[b * L1 + q], acc);
        return;
    }

    // ======================= word blocks =================================
    uint32_t* smA = (uint32_t*)smem;
    float* sF  = (float*)(smem + OFF_F);
    float* sV  = (float*)(smem + OFF_V);
    float* sSc = (float*)(smem + OFF_SC);
    float* sRd = (float*)(smem + OFF_RD);

    const int wid    = tid >> 5;       // 0..15
    const int lane   = tid & 31;
    const int g      = lane >> 2;
    const int tg     = lane & 3;
    const int warp_m = wid >> 2;       // 0..3  (32-row slices)
    const int warp_n = wid & 3;        // 0..3  (64-col slices)
    const int bq     = blockIdx.x;
    const int b      = bq >> 5;

    const uint32_t smA_u32 = smem_u32(smA);
    const uint32_t smB_u32 = smem_u32(smem + OFF_BBUF);

    // ldmatrix per-thread address components (mapping validated since R5)
    const int r8   = lane & 7;
    const int hsel = (lane >> 3) & 1;
    const int qsel = lane >> 4;
    const uint32_t aLm = smA_u32 +
        (((warp_m * 32 + r8 + hsel * 8) * AW) + qsel * 4) * 4;
    const uint32_t bLm = smB_u32 +
        (((warp_n * 64 + r8 + qsel * 8) * BW) + hsel * 4) * 4;

    // ---- issue B chunks 0,1 (1024 float4 per chunk; 2 per thread) ----
#pragma unroll
    for (int c = 0; c < 2; ++c) {
#pragma unroll
        for (int i = 0; i < 2; ++i) {
            int idx = tid + 512 * i, row = idx >> 2, q = idx & 3;
            const uint32_t* gp = g_Wmh + (size_t)row * 256 + c * 16 + q * 4;
            CP_ASYNC16(smB_u32 + c * BBUF_BYTES + (row * BW + q * 4) * 4, gp);
        }
        CP_COMMIT();
    }

    // ---- A tile resident load + convert ----
    {
        const float4* A4 = (const float4*)(wmem + (size_t)bq * L2 * MEMD);
#pragma unroll 4
        for (int i = 0; i < 32; ++i) {
            int idx = tid + 512 * i;          // 16384 float4
            int row = idx >> 7, c = idx & 127;
            float4 v = A4[idx];
            uint32_t* dst = smA + row * AW + c * 2;
            dst[0] = pack_h2(v.x, v.y);
            dst[1] = pack_h2(v.z, v.w);
        }
    }
    if (tid < DEC) {
        const int fi = b * DEC + tid;
        float f1v = 0.f;
#pragma unroll
        for (int p = 0; p < 8; ++p) f1v += g_f1p[p * (BB * DEC) + fi];
        sF[tid] = f1v;
        sV[tid] = Wv[tid];
    }
    if (tid < L2) sSc[tid] = 0.f;
    __syncthreads();   // A tile + sF/sV visible

    for (int ntc = 0; ntc < 2; ++ntc) {
        float acc[2][8][4];
#pragma unroll
        for (int mt = 0; mt < 2; ++mt)
#pragma unroll
            for (int nt = 0; nt < 8; ++nt)
#pragma unroll
                for (int i = 0; i < 4; ++i) acc[mt][nt][i] = 0.f;

        for (int kc = 0; kc < 16; ++kc) {
            const int c = ntc * 16 + kc;
            if (c >= 30) { CP_WAIT0(); } else { CP_WAIT1(); }   // chunk c ready
            __syncthreads();                                    // past reads done
            if (c + 2 < 32) {                                   // refill (c+2)%3
                const int cn = c + 2;
                const int d0 = (cn >> 4) * 256, kw = (cn & 15) * 16;
                const uint32_t bo = smB_u32 + (cn % 3) * BBUF_BYTES;
#pragma unroll
                for (int i = 0; i < 2; ++i) {
                    int idx = tid + 512 * i, row = idx >> 2, q = idx & 3;
                    const uint32_t* gp = g_Wmh + (size_t)(d0 + row) * 256 + kw + q * 4;
                    CP_ASYNC16(bo + (row * BW + q * 4) * 4, gp);
                }
                CP_COMMIT();
            }

            const uint32_t bufB = bLm + (c % 3) * BBUF_BYTES;
#pragma unroll
            for (int ks = 0; ks < 2; ++ks) {
                uint32_t af[2][4], bf[8][2];
#pragma unroll
                for (int mt = 0; mt < 2; ++mt)
                    LDSM_X4(af[mt][0], af[mt][1], af[mt][2], af[mt][3],
                            aLm + (mt * 16 * AW + kc * 16 + ks * 8) * 4);
#pragma unroll
                for (int p = 0; p < 4; ++p)
                    LDSM_X4(bf[2 * p][0], bf[2 * p][1],
                            bf[2 * p + 1][0], bf[2 * p + 1][1],
                            bufB + (p * 16 * BW + ks * 8) * 4);
#pragma unroll
                for (int mt = 0; mt < 2; ++mt)
#pragma unroll
                    for (int nt = 0; nt < 8; ++nt)
                        mma_f16(acc[mt][nt], af[mt], bf[nt]);
            }
        }

        // ---- epilogue: tanh + Wv dot into per-row partials ----
        float rs[2][2];
#pragma unroll
        for (int mt = 0; mt < 2; ++mt) { rs[mt][0] = 0.f; rs[mt][1] = 0.f; }
#pragma unroll
        for (int mt = 0; mt < 2; ++mt) {
#pragma unroll
            for (int nt = 0; nt < 8; ++nt) {
                const int d0 = ntc * 256 + warp_n * 64 + nt * 8 + 2 * tg;
                float w0 = sV[d0], w1 = sV[d0 + 1];
                float f0 = sF[d0], f1v = sF[d0 + 1];
                rs[mt][0] += tanh_hw(acc[mt][nt][0] + f0) * w0 +
                             tanh_hw(acc[mt][nt][1] + f1v) * w1;
                rs[mt][1] += tanh_hw(acc[mt][nt][2] + f0) * w0 +
                             tanh_hw(acc[mt][nt][3] + f1v) * w1;
            }
        }
#pragma unroll
        for (int ofs = 1; ofs <= 2; ofs <<= 1)
#pragma unroll
            for (int mt = 0; mt < 2; ++mt) {
                rs[mt][0] += __shfl_xor_sync(0xffffffffu, rs[mt][0], ofs);
                rs[mt][1] += __shfl_xor_sync(0xffffffffu, rs[mt][1], ofs);
            }
        if (tg == 0) {
#pragma unroll
            for (int mt = 0; mt < 2; ++mt) {
                atomicAdd(&sSc[warp_m * 32 + mt * 16 + g],     rs[mt][0]);
                atomicAdd(&sSc[warp_m * 32 + mt * 16 + 8 + g], rs[mt][1]);
            }
        }
    }
    __syncthreads();

    // ---- masked softmax over 128 words ----
    float s = -INFINITY;
    if (tid < L2) {
        s = sSc[tid];
        if (wmask[bq * L2 + tid] == 0) s = -INFINITY;
    }
    float m = s;
#pragma unroll
    for (int ofs = 16; ofs; ofs >>= 1)
        m = fmaxf(m, __shfl_xor_sync(0xffffffffu, m, ofs));
    if (lane == 0) sRd[wid] = m;
    __syncthreads();
    float bmax = sRd[0];
#pragma unroll
    for (int i = 1; i < 4; ++i) bmax = fmaxf(bmax, sRd[i]);

    float e = 0.f;
    if (tid < L2 && bmax > -INFINITY) e = expf(s - bmax);
    float t = e;
#pragma unroll
    for (int ofs = 16; ofs; ofs >>= 1)
        t += __shfl_xor_sync(0xffffffffu, t, ofs);
    __syncthreads();                 // sRd max reads done before overwrite
    if (lane == 0) sRd[wid] = t;
    __syncthreads();
    float bsum = 0.f;
#pragma unroll
    for (int i = 0; i < 4; ++i) bsum += sRd[i];

    float attn = 0.f;
    if (tid < L2) {
        attn = (bsum > 0.f) ? e / bsum : 0.f;
        attn_out[bq * L2 + tid] = attn;
    }
    __syncthreads();
    if (tid < L2) sSc[tid] = attn;
    __syncthreads();

    // ---- partial context from resident A tile (1 m-col per thread) ----
    {
        const int wsel = tid >> 1;      // half2 word within row
        const int hi   = tid & 1;
        float cm = 0.f;
#pragma unroll 8
        for (int w = 0; w < L2; ++w) {
            float a = sSc[w];
            uint32_t hv = smA[w * AW + wsel];
            __half2 h = *(__half2*)&hv;
            float2 f = __half22float2(h);
            cm = fmaf(a, hi ? f.y : f.x, cm);
        }
        g_ctxp[bq * MEMD + tid] = cm;
    }
}

// ---------------------------------------------------------------------------
// Kernel D (wide): grid 64 x 128 thr. Block (b, seg): per-b doc softmax
// (recomputed, cheap), ctx segment of 128 m-cols, resc scale of 1024 elems.
// ---------------------------------------------------------------------------
__global__ void combine_kernel(const int* __restrict__ dmask,
                               float* __restrict__ ctx,
                               float* __restrict__ resc) {
    __shared__ float sda[L1];
    const int b   = blockIdx.x >> 2;   // 16
    const int seg = blockIdx.x & 3;    // 4 segments
    const int tid = threadIdx.x;       // 128

    if (tid < L1) {
        float s = g_doc_score[b * L1 + tid];
        if (dmask[b * L1 + tid] == 0) s = -INFINITY;
        float m = s;
#pragma unroll
        for (int ofs = 16; ofs; ofs >>= 1)
            m = fmaxf(m, __shfl_xor_sync(0xffffffffu, m, ofs));
        float e = (m > -INFINITY) ? expf(s - m) : 0.f;
        float sum = e;
#pragma unroll
        for (int ofs = 16; ofs; ofs >>= 1)
            sum += __shfl_xor_sync(0xffffffffu, sum, ofs);
        sda[tid] = (sum > 0.f) ? e / sum : 0.f;
    }
    __syncthreads();

    const int m = seg * 128 + tid;     // ctx column
    float acc = 0.f;
#pragma unroll 8
    for (int q = 0; q < L1; ++q)
        acc = fmaf(sda[q], g_ctxp[(b * L1 + q) * MEMD + m], acc);
    ctx[b * MEMD + m] = acc;

#pragma unroll
    for (int i = 0; i < 8; ++i) {
        int idx = seg * 1024 + i * 128 + tid;    // 0..4095 within b
        resc[b * (L1 * L2) + idx] *= sda[idx >> 7];
    }
}

// ---------------------------------------------------------------------------
extern "C" void kernel_launch(void* const* d_in, const int* in_sizes, int n_in,
                              void* d_out, int out_size) {
    const float* decoder = (const float*)d_in[0];
    const float* dmem    = (const float*)d_in[1];
    const float* wmem    = (const float*)d_in[2];
    const float* topic   = (const float*)d_in[3];
    const int*   dmask   = (const int*)d_in[4];
    const int*   wmask   = (const int*)d_in[5];
    const float* Wv      = (const float*)d_in[6];
    const float* Wd      = (const float*)d_in[7];
    const float* Wt      = (const float*)d_in[8];
    const float* Wm      = (const float*)d_in[9];
    const float* Wv2     = (const float*)d_in[10];
    const float* Wd2     = (const float*)d_in[11];
    const float* Wt2     = (const float*)d_in[12];
    const float* Wm2     = (const float*)d_in[13];

    float* out  = (float*)d_out;
    float* ctx  = out;                  // context [16,512]
    float* resc = out + BB * MEMD;      // rescaled [16,32,128]

    cudaFuncSetAttribute(word_attn_tc,
                         cudaFuncAttributeMaxDynamicSharedMemorySize, SMEM_BYTES);

    prep_kernel<<<288, 256>>>(decoder, topic, Wd, Wt, Wd2, Wt2, Wm);
    word_attn_tc<<<BB * L1 + 128, 512, SMEM_BYTES>>>(
        wmem, Wv, wmask, resc, dmem, Wm2, Wv2);
    combine_kernel<<<64, 128>>>(dmask, ctx, resc);
}

// round 14
// speedup vs baseline: 1.1005x; 1.1005x over previous
#include <cuda_runtime.h>
#include <cuda_fp16.h>
#include <math.h>
#include <stdint.h>

#define BB 16
#define L1 32
#define L2 128
#define DEC 512
#define MEMD 512
#define TOPN 50
#define NPART 17                     // 16 K-split parts + 1 topic part

// Scratch (allocation-free rule: __device__ globals)
__device__ float    g_f1p[NPART * BB * DEC];
__device__ float    g_f2p[NPART * BB * DEC];
__device__ float    g_doc_score[BB * L1];
__device__ uint32_t g_Wmh[DEC * MEMD / 2];   // Wm as half2 pairs
__device__ float    g_ctxp[BB * L1 * MEMD];  // per-(b,q) partial context

// ============================ helpers =====================================
__device__ __forceinline__ uint32_t smem_u32(const void* p) {
    uint32_t a;
    asm("{ .reg .u64 t; cvta.to.shared.u64 t, %1; cvt.u32.u64 %0, t; }"
        : "=r"(a) : "l"(p));
    return a;
}
#define CP_ASYNC16(dst_u32, src_ptr) \
    asm volatile("cp.async.cg.shared.global [%0], [%1], 16;" \
                 :: "r"(dst_u32), "l"(src_ptr) : "memory")
#define CP_COMMIT() asm volatile("cp.async.commit_group;" ::: "memory")
#define CP_WAIT0()  asm volatile("cp.async.wait_group 0;" ::: "memory")
#define CP_WAIT1()  asm volatile("cp.async.wait_group 1;" ::: "memory")

#define LDSM_X4(R0, R1, R2, R3, addr) \
    asm volatile("ldmatrix.sync.aligned.m8n8.x4.shared.b16 {%0,%1,%2,%3}, [%4];" \
        : "=r"(R0), "=r"(R1), "=r"(R2), "=r"(R3) : "r"(addr))

__device__ __forceinline__ float tanh_hw(float x) {
    float y;
    asm("tanh.approx.f32 %0, %1;" : "=f"(y) : "f"(x));
    return y;
}

__device__ __forceinline__ void mma_f16(float* c, const uint32_t* a, const uint32_t* b) {
    asm volatile(
        "mma.sync.aligned.m16n8k16.row.col.f32.f16.f16.f32 "
        "{%0,%1,%2,%3}, {%4,%5,%6,%7}, {%8,%9}, {%0,%1,%2,%3};"
        : "+f"(c[0]), "+f"(c[1]), "+f"(c[2]), "+f"(c[3])
        : "r"(a[0]), "r"(a[1]), "r"(a[2]), "r"(a[3]), "r"(b[0]), "r"(b[1]));
}

__device__ __forceinline__ uint32_t pack_h2(float x, float y) {
    __half2 h = __floats2half2_rn(x, y);
    return *(uint32_t*)&h;
}

// ---------------------------------------------------------------------------
// Kernel A: grid 324 x 256, single wave.
// Blocks 0..63:   f1/f2 K-split. warp=(mat,kp,dgrp), d=dgrp*32+lane.
//                 W reads coalesced (lanes walk d); sdec reads are warp-
//                 uniform broadcasts (b,kp,m shared by all lanes).
// Blocks 64..67:  topic partials (part 16).
// Blocks 68..323: Wm -> fp16 conversion + zero doc scores.
// ---------------------------------------------------------------------------
__global__ void prep_kernel(const float* __restrict__ dec,
                            const float* __restrict__ topic,
                            const float* __restrict__ Wd,
                            const float* __restrict__ Wt,
                            const float* __restrict__ Wd2,
                            const float* __restrict__ Wt2,
                            const float* __restrict__ Wm) {
    __shared__ float sdec[BB * DEC];    // 32 KB (blocks 0..63)
    __shared__ float stop[BB * TOPN];   // 3.2 KB (blocks 64..67)
    const int tid = threadIdx.x;
    const int blk = blockIdx.x;

    if (blk >= 68) {
        // ---- Wm conversion blocks ----
        const int idx = (blk - 68) * 256 + tid;   // 0..65535
        float4 v = ((const float4*)Wm)[idx];
        g_Wmh[idx * 2]     = pack_h2(v.x, v.y);
        g_Wmh[idx * 2 + 1] = pack_h2(v.z, v.w);
        if (idx < BB * L1) g_doc_score[idx] = 0.f;
        return;
    }

    if (blk >= 64) {
        // ---- topic blocks: part 16 ----
        for (int i = tid; i < BB * TOPN; i += 256) stop[i] = topic[i];
        __syncthreads();
        const int mat = (blk - 64) >> 1;
        const int d   = ((blk - 64) & 1) * 256 + tid;
        const float* WT = (mat ? Wt2 : Wt) + (size_t)d * TOPN;
        float* out = (mat ? g_f2p : g_f1p) + 16 * (BB * DEC) + d;

        float f[BB];
#pragma unroll
        for (int b = 0; b < BB; ++b) f[b] = 0.f;
        for (int t = 0; t < TOPN; ++t) {
            float wt = WT[t];
#pragma unroll
            for (int b = 0; b < BB; ++b)
                f[b] += wt * stop[b * TOPN + t];
        }
#pragma unroll
        for (int b = 0; b < BB; ++b) out[b * DEC] = f[b];
        return;
    }

    // ---- f1/f2 blocks 0..63 ----
    for (int i = tid; i < BB * DEC / 4; i += 256)
        ((float4*)sdec)[i] = ((const float4*)dec)[i];
    __syncthreads();

    const int lane = tid & 31;
    const int wloc = tid >> 5;                 // 0..7
    const int wg   = blk * 8 + wloc;           // 0..511
    const int mat  = wg >> 8;                  // 0..1
    const int rw   = wg & 255;
    const int kp   = rw >> 4;                  // 0..15 (32-K segment)
    const int dgrp = rw & 15;
    const int d    = dgrp * 32 + lane;
    const int k0   = kp * 32;

    const float4* W4 = (const float4*)((mat ? Wd2 : Wd) + (size_t)d * DEC + k0);
    float* out = (mat ? g_f2p : g_f1p) + kp * (BB * DEC) + d;

    float f[BB];
#pragma unroll
    for (int b = 0; b < BB; ++b) f[b] = 0.f;

#pragma unroll
    for (int m = 0; m < 8; ++m) {
        float4 w = W4[m];
#pragma unroll
        for (int b = 0; b < BB; ++b) {
            // warp-uniform address -> broadcast LDS, no conflicts
            const float4 dv = *(const float4*)(sdec + b * DEC + k0 + m * 4);
            f[b] += w.x * dv.x + w.y * dv.y + w.z * dv.z + w.w * dv.w;
        }
    }
#pragma unroll
    for (int b = 0; b < BB; ++b)
        out[b * DEC] = f[b];
}

// ---------------------------------------------------------------------------
// Kernel B (fused, 512 threads = 16 warps, 4m x 4n, warp tile 32x64):
// blocks [0,512): word-level fp16 GEMM (ldmatrix + mma m16n8k16)
//   + tanh + Wv-reduce + softmax + partial context from resident A tile.
// blocks [512,640): doc-level partial scores.
// (Mainloop identical to the best-measured R7 configuration.)
// ---------------------------------------------------------------------------
#define AW 260                      // A row stride in 32-bit words
#define BW 20                       // B row stride in 32-bit words
#define BBUF_BYTES 20480            // 256*BW*4
#define OFF_BBUF 133120             // after A tile (128*260*4)
#define OFF_F    194560             // after 3 B buffers
#define OFF_V    196608
#define OFF_SC   198656
#define OFF_RD   199168
#define SMEM_BYTES 199296

__global__ __launch_bounds__(512, 1)
void word_attn_tc(const float* __restrict__ wmem,   // [B,L1,L2,MEM]
                  const float* __restrict__ Wv,     // [DEC]
                  const int*   __restrict__ wmask,  // [B,L1,L2]
                  float* __restrict__ attn_out,     // [B,L1,L2]
                  const float* __restrict__ dmem,   // [B,L1,MEM]
                  const float* __restrict__ Wm2,    // [DEC,MEM]
                  const float* __restrict__ Wv2) {  // [DEC]
    extern __shared__ char smem[];
    const int tid = threadIdx.x;

    // ======================= doc-score blocks ============================
    if (blockIdx.x >= BB * L1) {
        float* sdoc = (float*)smem;           // 32*512 floats = 64KB
        const int blk = blockIdx.x - BB * L1; // 0..127
        const int b   = blk >> 3;
        const int dc  = blk & 7;

        const float* drow = dmem + (size_t)b * L1 * MEMD;
        for (int i = tid; i < L1 * MEMD; i += 512) sdoc[i] = drow[i];
        __syncthreads();

        const int q    = tid >> 4;          // 0..31
        const int dsub = tid & 15;          // 4 d each
        float acc = 0.f;
        for (int k = 0; k < 4; ++k) {
            const int d = dc * 64 + dsub * 4 + k;
            const float4* w = (const float4*)(Wm2 + (size_t)d * MEMD);
            const float4* x = (const float4*)(sdoc + q * MEMD);
            float s0 = 0.f;
#pragma unroll 8
            for (int mm = 0; mm < 128; ++mm) {
                float4 wv = w[mm], xv = x[mm];
                s0 += wv.x * xv.x + wv.y * xv.y + wv.z * xv.z + wv.w * xv.w;
            }
            const int fi = b * DEC + d;
            float f2v = 0.f;
#pragma unroll
            for (int p = 0; p < NPART; ++p) f2v += g_f2p[p * (BB * DEC) + fi];
            acc += tanh_hw(s0 + f2v) * Wv2[d];
        }
        atomicAdd(&g_doc_score[b * L1 + q], acc);
        return;
    }

    // ======================= word blocks =================================
    uint32_t* smA = (uint32_t*)smem;
    float* sF  = (float*)(smem + OFF_F);
    float* sV  = (float*)(smem + OFF_V);
    float* sSc = (float*)(smem + OFF_SC);
    float* sRd = (float*)(smem + OFF_RD);

    const int wid    = tid >> 5;       // 0..15
    const int lane   = tid & 31;
    const int g      = lane >> 2;
    const int tg     = lane & 3;
    const int warp_m = wid >> 2;       // 0..3  (32-row slices)
    const int warp_n = wid & 3;        // 0..3  (64-col slices)
    const int bq     = blockIdx.x;
    const int b      = bq >> 5;

    const uint32_t smA_u32 = smem_u32(smA);
    const uint32_t smB_u32 = smem_u32(smem + OFF_BBUF);

    // ldmatrix per-thread address components (mapping validated since R5)
    const int r8   = lane & 7;
    const int hsel = (lane >> 3) & 1;
    const int qsel = lane >> 4;
    const uint32_t aLm = smA_u32 +
        (((warp_m * 32 + r8 + hsel * 8) * AW) + qsel * 4) * 4;
    const uint32_t bLm = smB_u32 +
        (((warp_n * 64 + r8 + qsel * 8) * BW) + hsel * 4) * 4;

    // ---- issue B chunks 0,1 (1024 float4 per chunk; 2 per thread) ----
#pragma unroll
    for (int c = 0; c < 2; ++c) {
#pragma unroll
        for (int i = 0; i < 2; ++i) {
            int idx = tid + 512 * i, row = idx >> 2, q = idx & 3;
            const uint32_t* gp = g_Wmh + (size_t)row * 256 + c * 16 + q * 4;
            CP_ASYNC16(smB_u32 + c * BBUF_BYTES + (row * BW + q * 4) * 4, gp);
        }
        CP_COMMIT();
    }

    // ---- A tile resident load + convert ----
    {
        const float4* A4 = (const float4*)(wmem + (size_t)bq * L2 * MEMD);
#pragma unroll 4
        for (int i = 0; i < 32; ++i) {
            int idx = tid + 512 * i;          // 16384 float4
            int row = idx >> 7, c = idx & 127;
            float4 v = A4[idx];
            uint32_t* dst = smA + row * AW + c * 2;
            dst[0] = pack_h2(v.x, v.y);
            dst[1] = pack_h2(v.z, v.w);
        }
    }
    if (tid < DEC) {
        const int fi = b * DEC + tid;
        float f1v = 0.f;
#pragma unroll
        for (int p = 0; p < NPART; ++p) f1v += g_f1p[p * (BB * DEC) + fi];
        sF[tid] = f1v;
        sV[tid] = Wv[tid];
    }
    if (tid < L2) sSc[tid] = 0.f;
    __syncthreads();   // A tile + sF/sV visible

    for (int ntc = 0; ntc < 2; ++ntc) {
        float acc[2][8][4];
#pragma unroll
        for (int mt = 0; mt < 2; ++mt)
#pragma unroll
            for (int nt = 0; nt < 8; ++nt)
#pragma unroll
                for (int i = 0; i < 4; ++i) acc[mt][nt][i] = 0.f;

        for (int kc = 0; kc < 16; ++kc) {
            const int c = ntc * 16 + kc;
            if (c >= 30) { CP_WAIT0(); } else { CP_WAIT1(); }   // chunk c ready
            __syncthreads();                                    // past reads done
            if (c + 2 < 32) {                                   // refill (c+2)%3
                const int cn = c + 2;
                const int d0 = (cn >> 4) * 256, kw = (cn & 15) * 16;
                const uint32_t bo = smB_u32 + (cn % 3) * BBUF_BYTES;
#pragma unroll
                for (int i = 0; i < 2; ++i) {
                    int idx = tid + 512 * i, row = idx >> 2, q = idx & 3;
                    const uint32_t* gp = g_Wmh + (size_t)(d0 + row) * 256 + kw + q * 4;
                    CP_ASYNC16(bo + (row * BW + q * 4) * 4, gp);
                }
                CP_COMMIT();
            }

            const uint32_t bufB = bLm + (c % 3) * BBUF_BYTES;
#pragma unroll
            for (int ks = 0; ks < 2; ++ks) {
                uint32_t af[2][4], bf[8][2];
#pragma unroll
                for (int mt = 0; mt < 2; ++mt)
                    LDSM_X4(af[mt][0], af[mt][1], af[mt][2], af[mt][3],
                            aLm + (mt * 16 * AW + kc * 16 + ks * 8) * 4);
#pragma unroll
                for (int p = 0; p < 4; ++p)
                    LDSM_X4(bf[2 * p][0], bf[2 * p][1],
                            bf[2 * p + 1][0], bf[2 * p + 1][1],
                            bufB + (p * 16 * BW + ks * 8) * 4);
#pragma unroll
                for (int mt = 0; mt < 2; ++mt)
#pragma unroll
                    for (int nt = 0; nt < 8; ++nt)
                        mma_f16(acc[mt][nt], af[mt], bf[nt]);
            }
        }

        // ---- epilogue: tanh + Wv dot into per-row partials ----
        float rs[2][2];
#pragma unroll
        for (int mt = 0; mt < 2; ++mt) { rs[mt][0] = 0.f; rs[mt][1] = 0.f; }
#pragma unroll
        for (int mt = 0; mt < 2; ++mt) {
#pragma unroll
            for (int nt = 0; nt < 8; ++nt) {
                const int d0 = ntc * 256 + warp_n * 64 + nt * 8 + 2 * tg;
                float w0 = sV[d0], w1 = sV[d0 + 1];
                float f0 = sF[d0], f1v = sF[d0 + 1];
                rs[mt][0] += tanh_hw(acc[mt][nt][0] + f0) * w0 +
                             tanh_hw(acc[mt][nt][1] + f1v) * w1;
                rs[mt][1] += tanh_hw(acc[mt][nt][2] + f0) * w0 +
                             tanh_hw(acc[mt][nt][3] + f1v) * w1;
            }
        }
#pragma unroll
        for (int ofs = 1; ofs <= 2; ofs <<= 1)
#pragma unroll
            for (int mt = 0; mt < 2; ++mt) {
                rs[mt][0] += __shfl_xor_sync(0xffffffffu, rs[mt][0], ofs);
                rs[mt][1] += __shfl_xor_sync(0xffffffffu, rs[mt][1], ofs);
            }
        if (tg == 0) {
#pragma unroll
            for (int mt = 0; mt < 2; ++mt) {
                atomicAdd(&sSc[warp_m * 32 + mt * 16 + g],     rs[mt][0]);
                atomicAdd(&sSc[warp_m * 32 + mt * 16 + 8 + g], rs[mt][1]);
            }
        }
    }
    __syncthreads();

    // ---- masked softmax over 128 words ----
    float s = -INFINITY;
    if (tid < L2) {
        s = sSc[tid];
        if (wmask[bq * L2 + tid] == 0) s = -INFINITY;
    }
    float m = s;
#pragma unroll
    for (int ofs = 16; ofs; ofs >>= 1)
        m = fmaxf(m, __shfl_xor_sync(0xffffffffu, m, ofs));
    if (lane == 0) sRd[wid] = m;
    __syncthreads();
    float bmax = sRd[0];
#pragma unroll
    for (int i = 1; i < 4; ++i) bmax = fmaxf(bmax, sRd[i]);

    float e = 0.f;
    if (tid < L2 && bmax > -INFINITY) e = expf(s - bmax);
    float t = e;
#pragma unroll
    for (int ofs = 16; ofs; ofs >>= 1)
        t += __shfl_xor_sync(0xffffffffu, t, ofs);
    __syncthreads();                 // sRd max reads done before overwrite
    if (lane == 0) sRd[wid] = t;
    __syncthreads();
    float bsum = 0.f;
#pragma unroll
    for (int i = 0; i < 4; ++i) bsum += sRd[i];

    float attn = 0.f;
    if (tid < L2) {
        attn = (bsum > 0.f) ? e / bsum : 0.f;
        attn_out[bq * L2 + tid] = attn;
    }
    __syncthreads();
    if (tid < L2) sSc[tid] = attn;
    __syncthreads();

    // ---- partial context from resident A tile (1 m-col per thread) ----
    {
        const int wsel = tid >> 1;      // half2 word within row
        const int hi   = tid & 1;
        float cm = 0.f;
#pragma unroll 8
        for (int w = 0; w < L2; ++w) {
            float a = sSc[w];
            uint32_t hv = smA[w * AW + wsel];
            __half2 h = *(__half2*)&hv;
            float2 f = __half22float2(h);
            cm = fmaf(a, hi ? f.y : f.x, cm);
        }
        g_ctxp[bq * MEMD + tid] = cm;
    }
}

// ---------------------------------------------------------------------------
// Kernel D (wide): grid 64 x 128 thr. Block (b, seg): per-b doc softmax
// (recomputed, cheap), ctx segment of 128 m-cols, resc scale of 1024 elems.
// ---------------------------------------------------------------------------
__global__ void combine_kernel(const int* __restrict__ dmask,
                               float* __restrict__ ctx,
                               float* __restrict__ resc) {
    __shared__ float sda[L1];
    const int b   = blockIdx.x >> 2;   // 16
    const int seg = blockIdx.x & 3;    // 4 segments
    const int tid = threadIdx.x;       // 128

    if (tid < L1) {
        float s = g_doc_score[b * L1 + tid];
        if (dmask[b * L1 + tid] == 0) s = -INFINITY;
        float m = s;
#pragma unroll
        for (int ofs = 16; ofs; ofs >>= 1)
            m = fmaxf(m, __shfl_xor_sync(0xffffffffu, m, ofs));
        float e = (m > -INFINITY) ? expf(s - m) : 0.f;
        float sum = e;
#pragma unroll
        for (int ofs = 16; ofs; ofs >>= 1)
            sum += __shfl_xor_sync(0xffffffffu, sum, ofs);
        sda[tid] = (sum > 0.f) ? e / sum : 0.f;
    }
    __syncthreads();

    const int m = seg * 128 + tid;     // ctx column
    float acc = 0.f;
#pragma unroll 8
    for (int q = 0; q < L1; ++q)
        acc = fmaf(sda[q], g_ctxp[(b * L1 + q) * MEMD + m], acc);
    ctx[b * MEMD + m] = acc;

#pragma unroll
    for (int i = 0; i < 8; ++i) {
        int idx = seg * 1024 + i * 128 + tid;    // 0..4095 within b
        resc[b * (L1 * L2) + idx] *= sda[idx >> 7];
    }
}

// ---------------------------------------------------------------------------
extern "C" void kernel_launch(void* const* d_in, const int* in_sizes, int n_in,
                              void* d_out, int out_size) {
    const float* decoder = (const float*)d_in[0];
    const float* dmem    = (const float*)d_in[1];
    const float* wmem    = (const float*)d_in[2];
    const float* topic   = (const float*)d_in[3];
    const int*   dmask   = (const int*)d_in[4];
    const int*   wmask   = (const int*)d_in[5];
    const float* Wv      = (const float*)d_in[6];
    const float* Wd      = (const float*)d_in[7];
    const float* Wt      = (const float*)d_in[8];
    const float* Wm      = (const float*)d_in[9];
    const float* Wv2     = (const float*)d_in[10];
    const float* Wd2     = (const float*)d_in[11];
    const float* Wt2     = (const float*)d_in[12];
    const float* Wm2     = (const float*)d_in[13];

    float* out  = (float*)d_out;
    float* ctx  = out;                  // context [16,512]
    float* resc = out + BB * MEMD;      // rescaled [16,32,128]

    cudaFuncSetAttribute(word_attn_tc,
                         cudaFuncAttributeMaxDynamicSharedMemorySize, SMEM_BYTES);

    prep_kernel<<<324, 256>>>(decoder, topic, Wd, Wt, Wd2, Wt2, Wm);
    word_attn_tc<<<BB * L1 + 128, 512, SMEM_BYTES>>>(
        wmem, Wv, wmask, resc, dmem, Wm2, Wv2);
    combine_kernel<<<64, 128>>>(dmask, ctx, resc);
}

// round 15
// speedup vs baseline: 1.1088x; 1.0076x over previous
#include <cuda_runtime.h>
#include <cuda_fp16.h>
#include <math.h>
#include <stdint.h>

#define BB 16
#define L1 32
#define L2 128
#define DEC 512
#define MEMD 512
#define TOPN 50

// Scratch (allocation-free rule: __device__ globals)
__device__ float    g_f1[BB * DEC];
__device__ float    g_f2[BB * DEC];
__device__ float    g_doc_score[BB * L1];
__device__ uint32_t g_Wmh[DEC * MEMD / 2];   // Wm as half2 pairs
__device__ float    g_ctxp[BB * L1 * MEMD];  // per-(b,q) partial context

// ============================ helpers =====================================
__device__ __forceinline__ uint32_t smem_u32(const void* p) {
    uint32_t a;
    asm("{ .reg .u64 t; cvta.to.shared.u64 t, %1; cvt.u32.u64 %0, t; }"
        : "=r"(a) : "l"(p));
    return a;
}
#define CP_ASYNC16(dst_u32, src_ptr) \
    asm volatile("cp.async.cg.shared.global [%0], [%1], 16;" \
                 :: "r"(dst_u32), "l"(src_ptr) : "memory")
#define CP_COMMIT() asm volatile("cp.async.commit_group;" ::: "memory")
#define CP_WAIT0()  asm volatile("cp.async.wait_group 0;" ::: "memory")
#define CP_WAIT1()  asm volatile("cp.async.wait_group 1;" ::: "memory")

#define LDSM_X4(R0, R1, R2, R3, addr) \
    asm volatile("ldmatrix.sync.aligned.m8n8.x4.shared.b16 {%0,%1,%2,%3}, [%4];" \
        : "=r"(R0), "=r"(R1), "=r"(R2), "=r"(R3) : "r"(addr))

__device__ __forceinline__ float tanh_hw(float x) {
    float y;
    asm("tanh.approx.f32 %0, %1;" : "=f"(y) : "f"(x));
    return y;
}

__device__ __forceinline__ void mma_f16(float* c, const uint32_t* a, const uint32_t* b) {
    asm volatile(
        "mma.sync.aligned.m16n8k16.row.col.f32.f16.f16.f32 "
        "{%0,%1,%2,%3}, {%4,%5,%6,%7}, {%8,%9}, {%0,%1,%2,%3};"
        : "+f"(c[0]), "+f"(c[1]), "+f"(c[2]), "+f"(c[3])
        : "r"(a[0]), "r"(a[1]), "r"(a[2]), "r"(a[3]), "r"(b[0]), "r"(b[1]));
}

__device__ __forceinline__ uint32_t pack_h2(float x, float y) {
    __half2 h = __floats2half2_rn(x, y);
    return *(uint32_t*)&h;
}

// ---------------------------------------------------------------------------
// Kernel A: grid 384 x 256, single wave, no static smem.
// Blocks 0..127:   f1/f2. warp=(mat,d); lanes walk k (coalesced W+dec reads),
//                  16 fp32 accumulators (one per b), shfl_xor tree reduce,
//                  lanes 0..15 write the final f[b][d]. Topic folded in.
// Blocks 128..383: Wm -> fp16 conversion + zero doc scores.
// ---------------------------------------------------------------------------
__global__ void prep_kernel(const float* __restrict__ dec,
                            const float* __restrict__ topic,
                            const float* __restrict__ Wd,
                            const float* __restrict__ Wt,
                            const float* __restrict__ Wd2,
                            const float* __restrict__ Wt2,
                            const float* __restrict__ Wm) {
    const int tid = threadIdx.x;
    const int blk = blockIdx.x;

    if (blk >= 128) {
        // ---- Wm conversion blocks ----
        const int idx = (blk - 128) * 256 + tid;   // 0..65535
        float4 v = ((const float4*)Wm)[idx];
        g_Wmh[idx * 2]     = pack_h2(v.x, v.y);
        g_Wmh[idx * 2 + 1] = pack_h2(v.z, v.w);
        if (idx < BB * L1) g_doc_score[idx] = 0.f;
        return;
    }

    // ---- f1/f2 warps ----
    const int lane = tid & 31;
    const int w    = blk * 8 + (tid >> 5);     // 0..1023
    const int mat  = w >> 9;                   // 0: f1, 1: f2
    const int d    = w & 511;

    const float4* W4 = (const float4*)((mat ? Wd2 : Wd) + (size_t)d * DEC);
    float4 wreg[4];
#pragma unroll
    for (int m = 0; m < 4; ++m)
        wreg[m] = W4[m * 32 + lane];           // lanes consecutive: coalesced

    float f[BB];
#pragma unroll
    for (int b = 0; b < BB; ++b) f[b] = 0.f;

#pragma unroll
    for (int b = 0; b < BB; ++b) {
        const float4* D4 = (const float4*)(dec + b * DEC);
#pragma unroll
        for (int m = 0; m < 4; ++m) {
            float4 dv = D4[m * 32 + lane];     // coalesced, L1-hot
            f[b] += wreg[m].x * dv.x + wreg[m].y * dv.y +
                    wreg[m].z * dv.z + wreg[m].w * dv.w;
        }
    }

    // topic term: lanes walk t (coalesced)
    {
        const float* WT = (mat ? Wt2 : Wt) + (size_t)d * TOPN;
        float wt = WT[lane];
#pragma unroll
        for (int b = 0; b < BB; ++b)
            f[b] += wt * topic[b * TOPN + lane];
        if (lane < TOPN - 32) {
            float wt2v = WT[lane + 32];
#pragma unroll
            for (int b = 0; b < BB; ++b)
                f[b] += wt2v * topic[b * TOPN + lane + 32];
        }
    }

    // cross-lane reduce: all lanes end with full sums
#pragma unroll
    for (int ofs = 16; ofs; ofs >>= 1)
#pragma unroll
        for (int b = 0; b < BB; ++b)
            f[b] += __shfl_xor_sync(0xffffffffu, f[b], ofs);

    if (lane < BB)
        (mat ? g_f2 : g_f1)[lane * DEC + d] = f[lane];
}

// ---------------------------------------------------------------------------
// Kernel B (fused, 512 threads = 16 warps, 4m x 4n, warp tile 32x64):
// blocks [0,512): word-level fp16 GEMM (ldmatrix + mma m16n8k16)
//   + tanh + Wv-reduce + softmax + partial context from resident A tile.
// blocks [512,640): doc-level partial scores.
// (Mainloop identical to the best-measured R7 configuration.)
// ---------------------------------------------------------------------------
#define AW 260                      // A row stride in 32-bit words
#define BW 20                       // B row stride in 32-bit words
#define BBUF_BYTES 20480            // 256*BW*4
#define OFF_BBUF 133120             // after A tile (128*260*4)
#define OFF_F    194560             // after 3 B buffers
#define OFF_V    196608
#define OFF_SC   198656
#define OFF_RD   199168
#define SMEM_BYTES 199296

__global__ __launch_bounds__(512, 1)
void word_attn_tc(const float* __restrict__ wmem,   // [B,L1,L2,MEM]
                  const float* __restrict__ Wv,     // [DEC]
                  const int*   __restrict__ wmask,  // [B,L1,L2]
                  float* __restrict__ attn_out,     // [B,L1,L2]
                  const float* __restrict__ dmem,   // [B,L1,MEM]
                  const float* __restrict__ Wm2,    // [DEC,MEM]
                  const float* __restrict__ Wv2) {  // [DEC]
    extern __shared__ char smem[];
    const int tid = threadIdx.x;

    // ======================= doc-score blocks ============================
    if (blockIdx.x >= BB * L1) {
        float* sdoc = (float*)smem;           // 32*512 floats = 64KB
        const int blk = blockIdx.x - BB * L1; // 0..127
        const int b   = blk >> 3;
        const int dc  = blk & 7;

        const float* drow = dmem + (size_t)b * L1 * MEMD;
        for (int i = tid; i < L1 * MEMD; i += 512) sdoc[i] = drow[i];
        __syncthreads();

        const int q    = tid >> 4;          // 0..31
        const int dsub = tid & 15;          // 4 d each
        float acc = 0.f;
        for (int k = 0; k < 4; ++k) {
            const int d = dc * 64 + dsub * 4 + k;
            const float4* w = (const float4*)(Wm2 + (size_t)d * MEMD);
            const float4* x = (const float4*)(sdoc + q * MEMD);
            float s0 = 0.f;
#pragma unroll 8
            for (int mm = 0; mm < 128; ++mm) {
                float4 wv = w[mm], xv = x[mm];
                s0 += wv.x * xv.x + wv.y * xv.y + wv.z * xv.z + wv.w * xv.w;
            }
            acc += tanh_hw(s0 + g_f2[b * DEC + d]) * Wv2[d];
        }
        atomicAdd(&g_doc_score[b * L1 + q], acc);
        return;
    }

    // ======================= word blocks =================================
    uint32_t* smA = (uint32_t*)smem;
    float* sF  = (float*)(smem + OFF_F);
    float* sV  = (float*)(smem + OFF_V);
    float* sSc = (float*)(smem + OFF_SC);
    float* sRd = (float*)(smem + OFF_RD);

    const int wid    = tid >> 5;       // 0..15
    const int lane   = tid & 31;
    const int g      = lane >> 2;
    const int tg     = lane & 3;
    const int warp_m = wid >> 2;       // 0..3  (32-row slices)
    const int warp_n = wid & 3;        // 0..3  (64-col slices)
    const int bq     = blockIdx.x;
    const int b      = bq >> 5;

    const uint32_t smA_u32 = smem_u32(smA);
    const uint32_t smB_u32 = smem_u32(smem + OFF_BBUF);

    // ldmatrix per-thread address components (mapping validated since R5)
    const int r8   = lane & 7;
    const int hsel = (lane >> 3) & 1;
    const int qsel = lane >> 4;
    const uint32_t aLm = smA_u32 +
        (((warp_m * 32 + r8 + hsel * 8) * AW) + qsel * 4) * 4;
    const uint32_t bLm = smB_u32 +
        (((warp_n * 64 + r8 + qsel * 8) * BW) + hsel * 4) * 4;

    // ---- issue B chunks 0,1 (1024 float4 per chunk; 2 per thread) ----
#pragma unroll
    for (int c = 0; c < 2; ++c) {
#pragma unroll
        for (int i = 0; i < 2; ++i) {
            int idx = tid + 512 * i, row = idx >> 2, q = idx & 3;
            const uint32_t* gp = g_Wmh + (size_t)row * 256 + c * 16 + q * 4;
            CP_ASYNC16(smB_u32 + c * BBUF_BYTES + (row * BW + q * 4) * 4, gp);
        }
        CP_COMMIT();
    }

    // ---- A tile resident load + convert ----
    {
        const float4* A4 = (const float4*)(wmem + (size_t)bq * L2 * MEMD);
#pragma unroll 4
        for (int i = 0; i < 32; ++i) {
            int idx = tid + 512 * i;          // 16384 float4
            int row = idx >> 7, c = idx & 127;
            float4 v = A4[idx];
            uint32_t* dst = smA + row * AW + c * 2;
            dst[0] = pack_h2(v.x, v.y);
            dst[1] = pack_h2(v.z, v.w);
        }
    }
    if (tid < DEC) {
        sF[tid] = g_f1[b * DEC + tid];
        sV[tid] = Wv[tid];
    }
    if (tid < L2) sSc[tid] = 0.f;
    __syncthreads();   // A tile + sF/sV visible

    for (int ntc = 0; ntc < 2; ++ntc) {
        float acc[2][8][4];
#pragma unroll
        for (int mt = 0; mt < 2; ++mt)
#pragma unroll
            for (int nt = 0; nt < 8; ++nt)
#pragma unroll
                for (int i = 0; i < 4; ++i) acc[mt][nt][i] = 0.f;

        for (int kc = 0; kc < 16; ++kc) {
            const int c = ntc * 16 + kc;
            if (c >= 30) { CP_WAIT0(); } else { CP_WAIT1(); }   // chunk c ready
            __syncthreads();                                    // past reads done
            if (c + 2 < 32) {                                   // refill (c+2)%3
                const int cn = c + 2;
                const int d0 = (cn >> 4) * 256, kw = (cn & 15) * 16;
                const uint32_t bo = smB_u32 + (cn % 3) * BBUF_BYTES;
#pragma unroll
                for (int i = 0; i < 2; ++i) {
                    int idx = tid + 512 * i, row = idx >> 2, q = idx & 3;
                    const uint32_t* gp = g_Wmh + (size_t)(d0 + row) * 256 + kw + q * 4;
                    CP_ASYNC16(bo + (row * BW + q * 4) * 4, gp);
                }
                CP_COMMIT();
            }

            const uint32_t bufB = bLm + (c % 3) * BBUF_BYTES;
#pragma unroll
            for (int ks = 0; ks < 2; ++ks) {
                uint32_t af[2][4], bf[8][2];
#pragma unroll
                for (int mt = 0; mt < 2; ++mt)
                    LDSM_X4(af[mt][0], af[mt][1], af[mt][2], af[mt][3],
                            aLm + (mt * 16 * AW + kc * 16 + ks * 8) * 4);
#pragma unroll
                for (int p = 0; p < 4; ++p)
                    LDSM_X4(bf[2 * p][0], bf[2 * p][1],
                            bf[2 * p + 1][0], bf[2 * p + 1][1],
                            bufB + (p * 16 * BW + ks * 8) * 4);
#pragma unroll
                for (int mt = 0; mt < 2; ++mt)
#pragma unroll
                    for (int nt = 0; nt < 8; ++nt)
                        mma_f16(acc[mt][nt], af[mt], bf[nt]);
            }
        }

        // ---- epilogue: tanh + Wv dot into per-row partials ----
        float rs[2][2];
#pragma unroll
        for (int mt = 0; mt < 2; ++mt) { rs[mt][0] = 0.f; rs[mt][1] = 0.f; }
#pragma unroll
        for (int mt = 0; mt < 2; ++mt) {
#pragma unroll
            for (int nt = 0; nt < 8; ++nt) {
                const int d0 = ntc * 256 + warp_n * 64 + nt * 8 + 2 * tg;
                float w0 = sV[d0], w1 = sV[d0 + 1];
                float f0 = sF[d0], f1v = sF[d0 + 1];
                rs[mt][0] += tanh_hw(acc[mt][nt][0] + f0) * w0 +
                             tanh_hw(acc[mt][nt][1] + f1v) * w1;
                rs[mt][1] += tanh_hw(acc[mt][nt][2] + f0) * w0 +
                             tanh_hw(acc[mt][nt][3] + f1v) * w1;
            }
        }
#pragma unroll
        for (int ofs = 1; ofs <= 2; ofs <<= 1)
#pragma unroll
            for (int mt = 0; mt < 2; ++mt) {
                rs[mt][0] += __shfl_xor_sync(0xffffffffu, rs[mt][0], ofs);
                rs[mt][1] += __shfl_xor_sync(0xffffffffu, rs[mt][1], ofs);
            }
        if (tg == 0) {
#pragma unroll
            for (int mt = 0; mt < 2; ++mt) {
                atomicAdd(&sSc[warp_m * 32 + mt * 16 + g],     rs[mt][0]);
                atomicAdd(&sSc[warp_m * 32 + mt * 16 + 8 + g], rs[mt][1]);
            }
        }
    }
    __syncthreads();

    // ---- masked softmax over 128 words ----
    float s = -INFINITY;
    if (tid < L2) {
        s = sSc[tid];
        if (wmask[bq * L2 + tid] == 0) s = -INFINITY;
    }
    float m = s;
#pragma unroll
    for (int ofs = 16; ofs; ofs >>= 1)
        m = fmaxf(m, __shfl_xor_sync(0xffffffffu, m, ofs));
    if (lane == 0) sRd[wid] = m;
    __syncthreads();
    float bmax = sRd[0];
#pragma unroll
    for (int i = 1; i < 4; ++i) bmax = fmaxf(bmax, sRd[i]);

    float e = 0.f;
    if (tid < L2 && bmax > -INFINITY) e = expf(s - bmax);
    float t = e;
#pragma unroll
    for (int ofs = 16; ofs; ofs >>= 1)
        t += __shfl_xor_sync(0xffffffffu, t, ofs);
    __syncthreads();                 // sRd max reads done before overwrite
    if (lane == 0) sRd[wid] = t;
    __syncthreads();
    float bsum = 0.f;
#pragma unroll
    for (int i = 0; i < 4; ++i) bsum += sRd[i];

    float attn = 0.f;
    if (tid < L2) {
        attn = (bsum > 0.f) ? e / bsum : 0.f;
        attn_out[bq * L2 + tid] = attn;
    }
    __syncthreads();
    if (tid < L2) sSc[tid] = attn;
    __syncthreads();

    // ---- partial context from resident A tile (1 m-col per thread) ----
    {
        const int wsel = tid >> 1;      // half2 word within row
        const int hi   = tid & 1;
        float cm = 0.f;
#pragma unroll 8
        for (int w = 0; w < L2; ++w) {
            float a = sSc[w];
            uint32_t hv = smA[w * AW + wsel];
            __half2 h = *(__half2*)&hv;
            float2 f = __half22float2(h);
            cm = fmaf(a, hi ? f.y : f.x, cm);
        }
        g_ctxp[bq * MEMD + tid] = cm;
    }
}

// ---------------------------------------------------------------------------
// Kernel D (wide): grid 64 x 128 thr. Block (b, seg): per-b doc softmax
// (recomputed, cheap), ctx segment of 128 m-cols, resc scale of 1024 elems.
// ---------------------------------------------------------------------------
__global__ void combine_kernel(const int* __restrict__ dmask,
                               float* __restrict__ ctx,
                               float* __restrict__ resc) {
    __shared__ float sda[L1];
    const int b   = blockIdx.x >> 2;   // 16
    const int seg = blockIdx.x & 3;    // 4 segments
    const int tid = threadIdx.x;       // 128

    if (tid < L1) {
        float s = g_doc_score[b * L1 + tid];
        if (dmask[b * L1 + tid] == 0) s = -INFINITY;
        float m = s;
#pragma unroll
        for (int ofs = 16; ofs; ofs >>= 1)
            m = fmaxf(m, __shfl_xor_sync(0xffffffffu, m, ofs));
        float e = (m > -INFINITY) ? expf(s - m) : 0.f;
        float sum = e;
#pragma unroll
        for (int ofs = 16; ofs; ofs >>= 1)
            sum += __shfl_xor_sync(0xffffffffu, sum, ofs);
        sda[tid] = (sum > 0.f) ? e / sum : 0.f;
    }
    __syncthreads();

    const int m = seg * 128 + tid;     // ctx column
    float acc = 0.f;
#pragma unroll 8
    for (int q = 0; q < L1; ++q)
        acc = fmaf(sda[q], g_ctxp[(b * L1 + q) * MEMD + m], acc);
    ctx[b * MEMD + m] = acc;

#pragma unroll
    for (int i = 0; i < 8; ++i) {
        int idx = seg * 1024 + i * 128 + tid;    // 0..4095 within b
        resc[b * (L1 * L2) + idx] *= sda[idx >> 7];
    }
}

// ---------------------------------------------------------------------------
extern "C" void kernel_launch(void* const* d_in, const int* in_sizes, int n_in,
                              void* d_out, int out_size) {
    const float* decoder = (const float*)d_in[0];
    const float* dmem    = (const float*)d_in[1];
    const float* wmem    = (const float*)d_in[2];
    const float* topic   = (const float*)d_in[3];
    const int*   dmask   = (const int*)d_in[4];
    const int*   wmask   = (const int*)d_in[5];
    const float* Wv      = (const float*)d_in[6];
    const float* Wd      = (const float*)d_in[7];
    const float* Wt      = (const float*)d_in[8];
    const float* Wm      = (const float*)d_in[9];
    const float* Wv2     = (const float*)d_in[10];
    const float* Wd2     = (const float*)d_in[11];
    const float* Wt2     = (const float*)d_in[12];
    const float* Wm2     = (const float*)d_in[13];

    float* out  = (float*)d_out;
    float* ctx  = out;                  // context [16,512]
    float* resc = out + BB * MEMD;      // rescaled [16,32,128]

    cudaFuncSetAttribute(word_attn_tc,
                         cudaFuncAttributeMaxDynamicSharedMemorySize, SMEM_BYTES);

    prep_kernel<<<384, 256>>>(decoder, topic, Wd, Wt, Wd2, Wt2, Wm);
    word_attn_tc<<<BB * L1 + 128, 512, SMEM_BYTES>>>(
        wmem, Wv, wmask, resc, dmem, Wm2, Wv2);
    combine_kernel<<<64, 128>>>(dmask, ctx, resc);
}